// round 13
// baseline (speedup 1.0000x reference)
#include <cuda_runtime.h>
#include <cuda_bf16.h>
#include <math.h>

#define ND 10000
#define NB_EMB 10000
#define NT_EMB 1000
#define H 64
#define CAP 256            // bucket capacity per dst (mean deg 100, max ~143)

// ---------------- device scratch ---------------------------------------------
__device__ int   g_cnt_b[ND];
__device__ int   g_cnt_t[ND];
__device__ int   g_bucket_b[ND * CAP];   // stores SRC index (id resolved in agg)
__device__ int   g_bucket_t[ND * CAP];
__device__ __nv_bfloat16 g_Rb[NB_EMB * H];
__device__ __nv_bfloat16 g_Rt[NT_EMB * H];
__device__ float g_B[ND * H];
__device__ float g_T[ND * H];
__device__ float2 g_W2[H * H];   // interleaved (0.5*Wb@Wu, 0.5*Wt@Wu)
__device__ float g_vbb[H];       // 0.5 * bb1 @ Wu1
__device__ float g_vbt[H];       // 0.5 * bt1 @ Wu1
__device__ float g_score[ND];

// ================= K0: zero counters (must precede scatter) ====================
__global__ void zero_kernel() {
    int i = blockIdx.x * blockDim.x + threadIdx.x;
    if (i < ND) { g_cnt_b[i] = 0; g_cnt_t[i] = 0; }
}

// ---------------- scatter body: store src (no ids gather), 8 edges/thread -----
__device__ __forceinline__ void scatter_body(
    const int* __restrict__ srcb, const int* __restrict__ dstb,
    const int* __restrict__ srct, const int* __restrict__ dstt,
    int n, int bid, int nblocks)
{
    int n8 = n >> 3;
    int total = 2 * n8;
    int g = bid * 256 + threadIdx.x;
    int stride = nblocks * 256;
    for (int i = g; i < total; i += stride) {
        int which = (i >= n8);
        int gg = which ? i - n8 : i;
        const int4* s4 = (const int4*)(which ? srct : srcb);
        const int4* d4 = (const int4*)(which ? dstt : dstb);
        int* cnt = which ? g_cnt_t : g_cnt_b;
        int* bkt = which ? g_bucket_t : g_bucket_b;
        int4 da = d4[gg * 2], db = d4[gg * 2 + 1];
        int4 sa = s4[gg * 2], sb = s4[gg * 2 + 1];
        int p0 = atomicAdd(&cnt[da.x], 1);
        int p1 = atomicAdd(&cnt[da.y], 1);
        int p2 = atomicAdd(&cnt[da.z], 1);
        int p3 = atomicAdd(&cnt[da.w], 1);
        int p4 = atomicAdd(&cnt[db.x], 1);
        int p5 = atomicAdd(&cnt[db.y], 1);
        int p6 = atomicAdd(&cnt[db.z], 1);
        int p7 = atomicAdd(&cnt[db.w], 1);
        bkt[da.x * CAP + p0] = sa.x;
        bkt[da.y * CAP + p1] = sa.y;
        bkt[da.z * CAP + p2] = sa.z;
        bkt[da.w * CAP + p3] = sa.w;
        bkt[db.x * CAP + p4] = sb.x;
        bkt[db.y * CAP + p5] = sb.y;
        bkt[db.z * CAP + p6] = sb.z;
        bkt[db.w * CAP + p7] = sb.w;
    }
    int rem = n & 7;
    if (g < rem) {
        int i = n - 1 - g;
        int pb = atomicAdd(&g_cnt_b[dstb[i]], 1);
        g_bucket_b[dstb[i] * CAP + pb] = srcb[i];
        int pt = atomicAdd(&g_cnt_t[dstt[i]], 1);
        g_bucket_t[dstt[i] * CAP + pt] = srct[i];
    }
}

// ================= K1: scatter || (weight fold + bf16 convert) ================
__global__ void k1_scatter_prep(
    const int* __restrict__ srcb, const int* __restrict__ dstb,
    const int* __restrict__ srct, const int* __restrict__ dstt,
    int n, int scB,
    const float* __restrict__ be, const float* __restrict__ te,
    const float* __restrict__ Wb, const float* __restrict__ bb,
    const float* __restrict__ Wt, const float* __restrict__ bt,
    const float* __restrict__ Wu)
{
    if (blockIdx.x < scB) {
        scatter_body(srcb, dstb, srct, dstt, n, blockIdx.x, scB);
    } else if (blockIdx.x < scB + 16) {
        int t = (blockIdx.x - scB) * 256 + threadIdx.x;   // 0..4095
        int k = t >> 6;
        int j = t & 63;
        float accb = 0.f, acct = 0.f;
        #pragma unroll 16
        for (int m = 0; m < 64; m++) {
            float u = __ldg(&Wu[m * 64 + j]);
            accb += __ldg(&Wb[k * 64 + m]) * u;
            acct += __ldg(&Wt[k * 64 + m]) * u;
        }
        float2 r; r.x = 0.5f * accb; r.y = 0.5f * acct;
        g_W2[k * 64 + j] = r;
    } else if (blockIdx.x == scB + 16) {
        int t = threadIdx.x;
        if (t < 128) {
            int which = t >> 6;                           // 0: vbb, 1: vbt
            int j = t & 63;
            const float* v = which ? bt : bb;
            float acc = 0.f;
            #pragma unroll 16
            for (int m = 0; m < 64; m++)
                acc += __ldg(&v[m]) * __ldg(&Wu[m * 64 + j]);
            (which ? g_vbt : g_vbb)[j] = 0.5f * acc;
        }
    } else {
        int pb = blockIdx.x - (scB + 17);
        int pgrid = gridDim.x - (scB + 17);
        int tid = pb * blockDim.x + threadIdx.x;
        int stride = pgrid * blockDim.x;
        for (int i = tid; i < NB_EMB * H; i += stride)
            g_Rb[i] = __float2bfloat16(fmaxf(be[i], 0.f));
        for (int i = tid; i < NT_EMB * H; i += stride)
            g_Rt[i] = __float2bfloat16(fmaxf(te[i], 0.f));
    }
}

// ================= K2: segment aggregation, one warp per dst ===================
// bucket holds src index; resolve emb row via ids[src] (warp-broadcast load).
__device__ __forceinline__ void agg_body(
    int d, const int* __restrict__ cnt, const int* __restrict__ bkt,
    const int* __restrict__ ids,
    const __nv_bfloat16* __restrict__ emb, float* out, int lane)
{
    int s = d * CAP;
    int n = cnt[d];
    float ax = 0.f, ay = 0.f;
    int i = 0;
    for (; i + 8 <= n; i += 8) {
        int sidx[8];
        #pragma unroll
        for (int k = 0; k < 8; k++) sidx[k] = __ldg(&bkt[s + i + k]);
        int id[8];
        #pragma unroll
        for (int k = 0; k < 8; k++) id[k] = __ldg(&ids[sidx[k]]);
        __nv_bfloat162 v[8];
        #pragma unroll
        for (int k = 0; k < 8; k++)
            v[k] = __ldg((const __nv_bfloat162*)(emb + (size_t)id[k] * H) + lane);
        #pragma unroll
        for (int k = 0; k < 8; k++) {
            float2 f = __bfloat1622float2(v[k]);
            ax += f.x; ay += f.y;
        }
    }
    for (; i < n; i++) {
        int id = __ldg(&ids[__ldg(&bkt[s + i])]);
        float2 f = __bfloat1622float2(
            __ldg((const __nv_bfloat162*)(emb + (size_t)id * H) + lane));
        ax += f.x; ay += f.y;
    }
    float2 r; r.x = ax; r.y = ay;
    ((float2*)(out + (size_t)d * H))[lane] = r;
}

__global__ void agg_kernel(const int* __restrict__ idsb,
                           const int* __restrict__ idst) {
    int gw = (blockIdx.x * blockDim.x + threadIdx.x) >> 5;
    int lane = threadIdx.x & 31;
    if (gw >= 2 * ND) return;
    if (gw < ND) agg_body(gw,      g_cnt_b, g_bucket_b, idsb, g_Rb, g_B, lane);
    else         agg_body(gw - ND, g_cnt_t, g_bucket_t, idst, g_Rt, g_T, lane);
}

// ================= K3: head — 4 rows per warp (best measured variant) =========
__global__ void head_kernel(const float* __restrict__ bu,
                            const float* __restrict__ oW1, const float* __restrict__ ob1,
                            const float* __restrict__ oW2, const float* __restrict__ ob2) {
    __shared__ float2 sW[64 * 64];    // 32 KB, (Wbu, Wtu) interleaved
    __shared__ float soW1[64 * 32];   // 8 KB
    __shared__ float svbb[64], svbt[64], sbu[64];
    __shared__ float soW2[32], sob1[32];
    __shared__ float sob2;

    int tid = threadIdx.x;
    for (int k = tid; k < 4096; k += 256) sW[k] = g_W2[k];
    for (int k = tid; k < 2048; k += 256) soW1[k] = __ldg(&oW1[k]);
    if (tid < 64) { svbb[tid] = g_vbb[tid]; svbt[tid] = g_vbt[tid]; sbu[tid] = __ldg(&bu[tid]); }
    if (tid < 32) { soW2[tid] = __ldg(&oW2[tid]); sob1[tid] = __ldg(&ob1[tid]); }
    if (tid == 0) sob2 = __ldg(ob2);
    __syncthreads();

    int w = tid >> 5;
    int lane = tid & 31;
    int j0 = lane, j1 = lane + 32;

    for (int base = (blockIdx.x * 8 + w) * 4; base < ND; base += gridDim.x * 32) {
        float xb0[4], xb1[4], xt0[4], xt1[4];
        float acc0[4], acc1[4];
        #pragma unroll
        for (int r = 0; r < 4; r++) {
            int row = base + r;
            int rv = (row < ND) ? row : base;   // clamp: duplicate work, guarded write
            xb0[r] = g_B[(size_t)rv * 64 + lane];
            xb1[r] = g_B[(size_t)rv * 64 + 32 + lane];
            xt0[r] = g_T[(size_t)rv * 64 + lane];
            xt1[r] = g_T[(size_t)rv * 64 + 32 + lane];
            float degb = (float)g_cnt_b[rv];
            float degt = (float)g_cnt_t[rv];
            acc0[r] = degb * svbb[j0] + degt * svbt[j0] + sbu[j0];
            acc1[r] = degb * svbb[j1] + degt * svbt[j1] + sbu[j1];
        }

        #pragma unroll
        for (int k = 0; k < 32; k++) {
            float2 w0 = sW[k * 64 + j0];
            float2 w1 = sW[k * 64 + j1];
            #pragma unroll
            for (int r = 0; r < 4; r++) {
                float xb = __shfl_sync(0xffffffffu, xb0[r], k);
                float xt = __shfl_sync(0xffffffffu, xt0[r], k);
                acc0[r] += xb * w0.x + xt * w0.y;
                acc1[r] += xb * w1.x + xt * w1.y;
            }
        }
        #pragma unroll
        for (int k = 0; k < 32; k++) {
            float2 w0 = sW[(k + 32) * 64 + j0];
            float2 w1 = sW[(k + 32) * 64 + j1];
            #pragma unroll
            for (int r = 0; r < 4; r++) {
                float xb = __shfl_sync(0xffffffffu, xb1[r], k);
                float xt = __shfl_sync(0xffffffffu, xt1[r], k);
                acc0[r] += xb * w0.x + xt * w0.y;
                acc1[r] += xb * w1.x + xt * w1.y;
            }
        }

        #pragma unroll
        for (int r = 0; r < 4; r++) {
            float d0 = fmaxf(acc0[r], 0.f);
            float d1 = fmaxf(acc1[r], 0.f);
            float h = sob1[lane];
            #pragma unroll
            for (int k = 0; k < 32; k++) {
                float dk = __shfl_sync(0xffffffffu, d0, k);
                h += dk * soW1[k * 32 + lane];
            }
            #pragma unroll
            for (int k = 0; k < 32; k++) {
                float dk = __shfl_sync(0xffffffffu, d1, k);
                h += dk * soW1[(k + 32) * 32 + lane];
            }
            h = fmaxf(h, 0.f);
            float p = h * soW2[lane];
            #pragma unroll
            for (int o = 16; o > 0; o >>= 1)
                p += __shfl_down_sync(0xffffffffu, p, o);
            if (lane == 0 && base + r < ND)
                g_score[base + r] = 1.f / (1.f + expf(-(p + sob2)));
        }
    }
}

// ================= K4: output gather, 2x int4 per thread ========================
__global__ void out_gather_kernel(const int* __restrict__ inst2type,
                                  float* __restrict__ out, int n) {
    int n8 = n >> 3;
    int i = blockIdx.x * blockDim.x + threadIdx.x;
    int stride = gridDim.x * blockDim.x;
    for (int g = i; g < n8; g += stride) {
        int4 t0 = ((const int4*)inst2type)[g * 2];
        int4 t1 = ((const int4*)inst2type)[g * 2 + 1];
        float4 r0, r1;
        r0.x = g_score[t0.x]; r0.y = g_score[t0.y];
        r0.z = g_score[t0.z]; r0.w = g_score[t0.w];
        r1.x = g_score[t1.x]; r1.y = g_score[t1.y];
        r1.z = g_score[t1.z]; r1.w = g_score[t1.w];
        ((float4*)out)[g * 2]     = r0;
        ((float4*)out)[g * 2 + 1] = r1;
    }
    int rem = n & 7;
    if (i < rem)
        out[n - 1 - i] = g_score[inst2type[n - 1 - i]];
}

// ================= launch ======================================================
extern "C" void kernel_launch(void* const* d_in, const int* in_sizes, int n_in,
                              void* d_out, int out_size) {
    const int*   bene_ids      = (const int*)d_in[0];
    const int*   treatment_ids = (const int*)d_in[2];
    const int*   b2d_src       = (const int*)d_in[3];
    const int*   b2d_dst       = (const int*)d_in[4];
    const int*   t2d_src       = (const int*)d_in[5];
    const int*   t2d_dst       = (const int*)d_in[6];
    const int*   inst2type     = (const int*)d_in[7];
    const float* bene_emb      = (const float*)d_in[8];
    const float* treat_emb     = (const float*)d_in[10];
    const float* Wb1 = (const float*)d_in[17];
    const float* bb1 = (const float*)d_in[18];
    const float* Wt1 = (const float*)d_in[19];
    const float* bt1 = (const float*)d_in[20];
    const float* Wu1 = (const float*)d_in[21];
    const float* bu1 = (const float*)d_in[22];
    const float* oW1 = (const float*)d_in[23];
    const float* ob1 = (const float*)d_in[24];
    const float* oW2 = (const float*)d_in[25];
    const float* ob2 = (const float*)d_in[26];

    int E     = in_sizes[3];
    int NINST = in_sizes[7];

    // K0: zero counters only (scatter's sole dependency)
    zero_kernel<<<(ND + 255) / 256, 256>>>();

    // K1: scatter (LTS-op-bound, now 2 ops/edge) || weight fold + bf16 convert
    {
        int scB = (2 * (E >> 3) + 255) / 256;
        if (scB > 2048) scB = 2048;
        if (scB < 1) scB = 1;
        int prepB = 64;
        k1_scatter_prep<<<scB + 17 + prepB, 256>>>(
            b2d_src, b2d_dst, t2d_src, t2d_dst, E, scB,
            bene_emb, treat_emb, Wb1, bb1, Wt1, bt1, Wu1);
    }
    // K2: aggregation (resolves ids via warp-broadcast loads)
    {
        int blocks = (2 * ND * 32 + 255) / 256;
        agg_kernel<<<blocks, 256>>>(bene_ids, treatment_ids);
    }
    // K3: head
    head_kernel<<<313, 256>>>(bu1, oW1, ob1, oW2, ob2);
    // K4: gather
    {
        int blocks = ((NINST >> 3) + 255) / 256;
        if (blocks < 1) blocks = 1;
        out_gather_kernel<<<blocks, 256>>>(inst2type, (float*)d_out, NINST);
    }
}

// round 14
// speedup vs baseline: 1.1033x; 1.1033x over previous
#include <cuda_runtime.h>
#include <cuda_bf16.h>
#include <math.h>

#define ND 10000
#define NB_EMB 10000
#define NT_EMB 1000
#define H 64
#define CAP 256            // bucket capacity per dst (mean deg 100, max ~143)

// ---------------- device scratch (zero-initialized at module load) ------------
__device__ int   g_cnt_b[ND];
__device__ int   g_cnt_t[ND];
__device__ int   g_bucket_b[ND * CAP];
__device__ int   g_bucket_t[ND * CAP];
__device__ __nv_bfloat16 g_Rb[NB_EMB * H];
__device__ __nv_bfloat16 g_Rt[NT_EMB * H];
__device__ float g_B[ND * H];
__device__ float g_T[ND * H];
__device__ float2 g_W2[H * H];   // interleaved (0.5*Wb@Wu, 0.5*Wt@Wu)
__device__ float g_vbb[H];       // 0.5 * bb1 @ Wu1
__device__ float g_vbt[H];       // 0.5 * bt1 @ Wu1
__device__ float g_score[ND];

// ---------------- scatter body (both edge sets), 8 edges/thread ---------------
__device__ __forceinline__ void scatter_body(
    const int* __restrict__ srcb, const int* __restrict__ dstb,
    const int* __restrict__ idsb,
    const int* __restrict__ srct, const int* __restrict__ dstt,
    const int* __restrict__ idst, int n, int bid, int nblocks)
{
    int n8 = n >> 3;
    int total = 2 * n8;
    int g = bid * 256 + threadIdx.x;
    int stride = nblocks * 256;
    for (int i = g; i < total; i += stride) {
        int which = (i >= n8);
        int gg = which ? i - n8 : i;
        const int4* s4 = (const int4*)(which ? srct : srcb);
        const int4* d4 = (const int4*)(which ? dstt : dstb);
        const int* ids = which ? idst : idsb;
        int* cnt = which ? g_cnt_t : g_cnt_b;
        int* bkt = which ? g_bucket_t : g_bucket_b;
        int4 da = d4[gg * 2], db = d4[gg * 2 + 1];
        int4 sa = s4[gg * 2], sb = s4[gg * 2 + 1];
        int p0 = atomicAdd(&cnt[da.x], 1);
        int p1 = atomicAdd(&cnt[da.y], 1);
        int p2 = atomicAdd(&cnt[da.z], 1);
        int p3 = atomicAdd(&cnt[da.w], 1);
        int p4 = atomicAdd(&cnt[db.x], 1);
        int p5 = atomicAdd(&cnt[db.y], 1);
        int p6 = atomicAdd(&cnt[db.z], 1);
        int p7 = atomicAdd(&cnt[db.w], 1);
        int v0 = __ldg(&ids[sa.x]);
        int v1 = __ldg(&ids[sa.y]);
        int v2 = __ldg(&ids[sa.z]);
        int v3 = __ldg(&ids[sa.w]);
        int v4 = __ldg(&ids[sb.x]);
        int v5 = __ldg(&ids[sb.y]);
        int v6 = __ldg(&ids[sb.z]);
        int v7 = __ldg(&ids[sb.w]);
        bkt[da.x * CAP + p0] = v0;
        bkt[da.y * CAP + p1] = v1;
        bkt[da.z * CAP + p2] = v2;
        bkt[da.w * CAP + p3] = v3;
        bkt[db.x * CAP + p4] = v4;
        bkt[db.y * CAP + p5] = v5;
        bkt[db.z * CAP + p6] = v6;
        bkt[db.w * CAP + p7] = v7;
    }
    int rem = n & 7;
    if (g < rem) {
        int i = n - 1 - g;
        int pb = atomicAdd(&g_cnt_b[dstb[i]], 1);
        g_bucket_b[dstb[i] * CAP + pb] = idsb[srcb[i]];
        int pt = atomicAdd(&g_cnt_t[dstt[i]], 1);
        g_bucket_t[dstt[i] * CAP + pt] = idst[srct[i]];
    }
}

// ================= K1: scatter || (weight fold + bf16 convert) ================
__global__ void k1_scatter_prep(
    const int* __restrict__ srcb, const int* __restrict__ dstb,
    const int* __restrict__ idsb,
    const int* __restrict__ srct, const int* __restrict__ dstt,
    const int* __restrict__ idst, int n, int scB,
    const float* __restrict__ be, const float* __restrict__ te,
    const float* __restrict__ Wb, const float* __restrict__ bb,
    const float* __restrict__ Wt, const float* __restrict__ bt,
    const float* __restrict__ Wu)
{
    if (blockIdx.x < scB) {
        scatter_body(srcb, dstb, idsb, srct, dstt, idst, n, blockIdx.x, scB);
    } else if (blockIdx.x < scB + 16) {
        int t = (blockIdx.x - scB) * 256 + threadIdx.x;   // 0..4095
        int k = t >> 6;
        int j = t & 63;
        float accb = 0.f, acct = 0.f;
        #pragma unroll 16
        for (int m = 0; m < 64; m++) {
            float u = __ldg(&Wu[m * 64 + j]);
            accb += __ldg(&Wb[k * 64 + m]) * u;
            acct += __ldg(&Wt[k * 64 + m]) * u;
        }
        float2 r; r.x = 0.5f * accb; r.y = 0.5f * acct;
        g_W2[k * 64 + j] = r;
    } else if (blockIdx.x == scB + 16) {
        int t = threadIdx.x;
        if (t < 128) {
            int which = t >> 6;                           // 0: vbb, 1: vbt
            int j = t & 63;
            const float* v = which ? bt : bb;
            float acc = 0.f;
            #pragma unroll 16
            for (int m = 0; m < 64; m++)
                acc += __ldg(&v[m]) * __ldg(&Wu[m * 64 + j]);
            (which ? g_vbt : g_vbb)[j] = 0.5f * acc;
        }
    } else {
        int pb = blockIdx.x - (scB + 17);
        int pgrid = gridDim.x - (scB + 17);
        int tid = pb * blockDim.x + threadIdx.x;
        int stride = pgrid * blockDim.x;
        for (int i = tid; i < NB_EMB * H; i += stride)
            g_Rb[i] = __float2bfloat16(fmaxf(be[i], 0.f));
        for (int i = tid; i < NT_EMB * H; i += stride)
            g_Rt[i] = __float2bfloat16(fmaxf(te[i], 0.f));
    }
}

// ================= K2: segment aggregation, one warp per dst ===================
__device__ __forceinline__ void agg_body(
    int d, const int* __restrict__ cnt, const int* __restrict__ bkt,
    const __nv_bfloat16* __restrict__ emb, float* out, int lane)
{
    int s = d * CAP;
    int n = cnt[d];
    float ax = 0.f, ay = 0.f;
    int i = 0;
    for (; i + 8 <= n; i += 8) {
        int id[8];
        #pragma unroll
        for (int k = 0; k < 8; k++) id[k] = __ldg(&bkt[s + i + k]);
        __nv_bfloat162 v[8];
        #pragma unroll
        for (int k = 0; k < 8; k++)
            v[k] = __ldg((const __nv_bfloat162*)(emb + (size_t)id[k] * H) + lane);
        #pragma unroll
        for (int k = 0; k < 8; k++) {
            float2 f = __bfloat1622float2(v[k]);
            ax += f.x; ay += f.y;
        }
    }
    for (; i < n; i++) {
        int id = __ldg(&bkt[s + i]);
        float2 f = __bfloat1622float2(
            __ldg((const __nv_bfloat162*)(emb + (size_t)id * H) + lane));
        ax += f.x; ay += f.y;
    }
    float2 r; r.x = ax; r.y = ay;
    ((float2*)(out + (size_t)d * H))[lane] = r;
}

__global__ void agg_kernel() {
    int gw = (blockIdx.x * blockDim.x + threadIdx.x) >> 5;
    int lane = threadIdx.x & 31;
    if (gw >= 2 * ND) return;
    if (gw < ND) agg_body(gw,      g_cnt_b, g_bucket_b, g_Rb, g_B, lane);
    else         agg_body(gw - ND, g_cnt_t, g_bucket_t, g_Rt, g_T, lane);
}

// ================= K3: head as tiled GEMM — 64 rows x 64 cols per block ========
// D[64r][64c] = X[64r][128k] @ W[128k][64c] + bias ; X = B||T, W = [Wbu;Wtu]
// then per-warp shuffle layers 2+3 on D in smem.
__global__ __launch_bounds__(256)
void head_kernel(const float* __restrict__ bu,
                 const float* __restrict__ oW1, const float* __restrict__ ob1,
                 const float* __restrict__ oW2, const float* __restrict__ ob2) {
    extern __shared__ float sm[];
    float* sXt  = sm;             // [128][64], reused as sD[64][64] after layer1
    float* sW   = sXt + 128 * 64; // [128][64]
    float* soW1 = sW + 128 * 64;  // [64*32]
    float* svbb = soW1 + 2048;    // 64
    float* svbt = svbb + 64;
    float* sbu  = svbt + 64;
    float* sdegb = sbu + 64;      // 64
    float* sdegt = sdegb + 64;    // 64
    float* soW2 = sdegt + 64;     // 32
    float* sob1 = soW2 + 32;      // 32
    float* sob2 = sob1 + 32;      // 1

    int tid = threadIdx.x;
    int base = blockIdx.x * 64;

    // ---- load weights: split interleaved float2 into stacked [Wbu;Wtu] ----
    for (int t = tid; t < 4096; t += 256) {
        float2 w = g_W2[t];
        int k = t >> 6, j = t & 63;
        sW[k * 64 + j]        = w.x;   // Wbu rows 0..63
        sW[(64 + k) * 64 + j] = w.y;   // Wtu rows 64..127
    }
    for (int t = tid; t < 2048; t += 256) soW1[t] = __ldg(&oW1[t]);
    if (tid < 64) {
        svbb[tid] = g_vbb[tid];
        svbt[tid] = g_vbt[tid];
        sbu[tid]  = __ldg(&bu[tid]);
        int rv = base + tid; if (rv >= ND) rv = ND - 1;
        sdegb[tid] = (float)g_cnt_b[rv];
        sdegt[tid] = (float)g_cnt_t[rv];
    }
    if (tid >= 64 && tid < 96)  soW2[tid - 64] = __ldg(&oW2[tid - 64]);
    if (tid >= 96 && tid < 128) sob1[tid - 96] = __ldg(&ob1[tid - 96]);
    if (tid == 128) *sob2 = __ldg(ob2);

    // ---- load X tile transposed: sXt[k][row], k<64 = B cols, k>=64 = T cols --
    {
        int row = tid >> 2;           // 0..63
        int cg  = tid & 3;            // col group: 16 cols
        int rv = base + row; if (rv >= ND) rv = ND - 1;
        const float4* bsrc = (const float4*)(g_B + (size_t)rv * 64 + cg * 16);
        const float4* tsrc = (const float4*)(g_T + (size_t)rv * 64 + cg * 16);
        #pragma unroll
        for (int q = 0; q < 4; q++) {
            float4 v = bsrc[q];
            int c = cg * 16 + q * 4;
            sXt[(c + 0) * 64 + row] = v.x;
            sXt[(c + 1) * 64 + row] = v.y;
            sXt[(c + 2) * 64 + row] = v.z;
            sXt[(c + 3) * 64 + row] = v.w;
        }
        #pragma unroll
        for (int q = 0; q < 4; q++) {
            float4 v = tsrc[q];
            int c = 64 + cg * 16 + q * 4;
            sXt[(c + 0) * 64 + row] = v.x;
            sXt[(c + 1) * 64 + row] = v.y;
            sXt[(c + 2) * 64 + row] = v.z;
            sXt[(c + 3) * 64 + row] = v.w;
        }
    }
    __syncthreads();

    // ---- layer 1: 16x16 threads, 4x4 register tile -----------------------
    int tx = tid & 15;
    int ty = tid >> 4;
    float acc[4][4];
    #pragma unroll
    for (int r = 0; r < 4; r++) {
        int rr = ty * 4 + r;
        #pragma unroll
        for (int c = 0; c < 4; c++) {
            int cc = tx * 4 + c;
            acc[r][c] = sdegb[rr] * svbb[cc] + sdegt[rr] * svbt[cc] + sbu[cc];
        }
    }
    #pragma unroll 4
    for (int k = 0; k < 128; k++) {
        float4 xv = *(const float4*)&sXt[k * 64 + ty * 4];
        float4 wv = *(const float4*)&sW[k * 64 + tx * 4];
        acc[0][0] += xv.x * wv.x; acc[0][1] += xv.x * wv.y;
        acc[0][2] += xv.x * wv.z; acc[0][3] += xv.x * wv.w;
        acc[1][0] += xv.y * wv.x; acc[1][1] += xv.y * wv.y;
        acc[1][2] += xv.y * wv.z; acc[1][3] += xv.y * wv.w;
        acc[2][0] += xv.z * wv.x; acc[2][1] += xv.z * wv.y;
        acc[2][2] += xv.z * wv.z; acc[2][3] += xv.z * wv.w;
        acc[3][0] += xv.w * wv.x; acc[3][1] += xv.w * wv.y;
        acc[3][2] += xv.w * wv.z; acc[3][3] += xv.w * wv.w;
    }
    __syncthreads();                 // done reading sXt; reuse as sD
    float* sD = sXt;                 // [64][64]
    #pragma unroll
    for (int r = 0; r < 4; r++) {
        #pragma unroll
        for (int c = 0; c < 4; c++)
            sD[(ty * 4 + r) * 64 + tx * 4 + c] = fmaxf(acc[r][c], 0.f);
    }
    __syncthreads();

    // ---- layers 2+3: per-warp shuffle, 8 rows per warp --------------------
    int w = tid >> 5;
    int lane = tid & 31;
    #pragma unroll
    for (int rr = 0; rr < 8; rr++) {
        int row = w * 8 + rr;
        float d0 = sD[row * 64 + lane];
        float d1 = sD[row * 64 + 32 + lane];
        float h = sob1[lane];
        #pragma unroll
        for (int k = 0; k < 32; k++) {
            float dk = __shfl_sync(0xffffffffu, d0, k);
            h += dk * soW1[k * 32 + lane];
        }
        #pragma unroll
        for (int k = 0; k < 32; k++) {
            float dk = __shfl_sync(0xffffffffu, d1, k);
            h += dk * soW1[(k + 32) * 32 + lane];
        }
        h = fmaxf(h, 0.f);
        float p = h * soW2[lane];
        #pragma unroll
        for (int o = 16; o > 0; o >>= 1)
            p += __shfl_down_sync(0xffffffffu, p, o);
        if (lane == 0 && base + row < ND)
            g_score[base + row] = 1.f / (1.f + expf(-(p + *sob2)));
    }
}

// ================= K4: output gather (+ counter re-zero for next call) =========
__global__ void out_gather_kernel(const int* __restrict__ inst2type,
                                  float* __restrict__ out, int n) {
    int gt = blockIdx.x * blockDim.x + threadIdx.x;
    int stride = gridDim.x * blockDim.x;
    // re-zero counters so every kernel_launch call starts from zero
    for (int i = gt; i < 2 * ND; i += stride) {
        if (i < ND) g_cnt_b[i] = 0;
        else        g_cnt_t[i - ND] = 0;
    }
    int n8 = n >> 3;
    for (int g = gt; g < n8; g += stride) {
        int4 t0 = ((const int4*)inst2type)[g * 2];
        int4 t1 = ((const int4*)inst2type)[g * 2 + 1];
        float4 r0, r1;
        r0.x = g_score[t0.x]; r0.y = g_score[t0.y];
        r0.z = g_score[t0.z]; r0.w = g_score[t0.w];
        r1.x = g_score[t1.x]; r1.y = g_score[t1.y];
        r1.z = g_score[t1.z]; r1.w = g_score[t1.w];
        ((float4*)out)[g * 2]     = r0;
        ((float4*)out)[g * 2 + 1] = r1;
    }
    int rem = n & 7;
    if (gt < rem)
        out[n - 1 - gt] = g_score[inst2type[n - 1 - gt]];
}

// ================= launch ======================================================
extern "C" void kernel_launch(void* const* d_in, const int* in_sizes, int n_in,
                              void* d_out, int out_size) {
    const int*   bene_ids      = (const int*)d_in[0];
    const int*   treatment_ids = (const int*)d_in[2];
    const int*   b2d_src       = (const int*)d_in[3];
    const int*   b2d_dst       = (const int*)d_in[4];
    const int*   t2d_src       = (const int*)d_in[5];
    const int*   t2d_dst       = (const int*)d_in[6];
    const int*   inst2type     = (const int*)d_in[7];
    const float* bene_emb      = (const float*)d_in[8];
    const float* treat_emb     = (const float*)d_in[10];
    const float* Wb1 = (const float*)d_in[17];
    const float* bb1 = (const float*)d_in[18];
    const float* Wt1 = (const float*)d_in[19];
    const float* bt1 = (const float*)d_in[20];
    const float* Wu1 = (const float*)d_in[21];
    const float* bu1 = (const float*)d_in[22];
    const float* oW1 = (const float*)d_in[23];
    const float* ob1 = (const float*)d_in[24];
    const float* oW2 = (const float*)d_in[25];
    const float* ob2 = (const float*)d_in[26];

    int E     = in_sizes[3];
    int NINST = in_sizes[7];

    // K1: scatter (counters are zero: module-load init / re-zeroed by K4)
    {
        int scB = (2 * (E >> 3) + 255) / 256;
        if (scB > 2048) scB = 2048;
        if (scB < 1) scB = 1;
        int prepB = 64;
        k1_scatter_prep<<<scB + 17 + prepB, 256>>>(
            b2d_src, b2d_dst, bene_ids, t2d_src, t2d_dst, treatment_ids, E, scB,
            bene_emb, treat_emb, Wb1, bb1, Wt1, bt1, Wu1);
    }
    // K2: aggregation
    {
        int blocks = (2 * ND * 32 + 255) / 256;
        agg_kernel<<<blocks, 256>>>();
    }
    // K3: head (tiled GEMM), 157 blocks x 64 rows, dynamic smem ~75 KB
    {
        size_t smem = (size_t)(128 * 64 + 128 * 64 + 2048 + 64 * 5 + 32 * 2 + 1)
                      * sizeof(float);
        static int configured = 0;
        if (!configured) {
            cudaFuncSetAttribute(head_kernel,
                                 cudaFuncAttributeMaxDynamicSharedMemorySize,
                                 (int)smem);
            configured = 1;
        }
        head_kernel<<<(ND + 63) / 64, 256, smem>>>(bu1, oW1, ob1, oW2, ob2);
    }
    // K4: gather + counter re-zero
    {
        int blocks = ((NINST >> 3) + 255) / 256;
        if (blocks < 1) blocks = 1;
        out_gather_kernel<<<blocks, 256>>>(inst2type, (float*)d_out, NINST);
    }
}